// round 2
// baseline (speedup 1.0000x reference)
#include <cuda_runtime.h>

#define SLEN  2048
#define BATCH 32
#define DDIM  1024
#define E2    1024
#define MROWS (SLEN*BATCH)

// Device-global scratch (no runtime allocation allowed).
__device__ float g_ws[BATCH*DDIM];     // weighted_s  [B, D]
__device__ float g_score[MROWS];       // score       [S*B] (r = s*32+b)
__device__ float g_attn[MROWS];        // softmax(score) over s

__device__ __forceinline__ unsigned f2tf32(float x){
    unsigned r; asm("cvt.rna.tf32.f32 %0, %1;" : "=r"(r) : "f"(x)); return r;
}
__device__ __forceinline__ float fast_tanh(float x){
    float r; asm("tanh.approx.f32 %0, %1;" : "=f"(r) : "f"(x)); return r;
}

// Zero score accumulator and output (both are atomicAdd targets).
__global__ void zero_kernel(float* __restrict__ out){
    int i = blockIdx.x*256 + threadIdx.x;
    if(i < MROWS)      g_score[i] = 0.f;
    if(i < BATCH*E2)   out[i]     = 0.f;
}

// ws[b,e] = sum_d h[b,d] * Wb[e,d].  One block per e-row of Wb; each warp
// holds the Wb row in registers and dots it against 4 h rows.
__global__ __launch_bounds__(256) void ws_kernel(const float* __restrict__ h,
                                                 const float* __restrict__ Wb){
    int e    = blockIdx.x;
    int w    = threadIdx.x >> 5;
    int lane = threadIdx.x & 31;
    float wreg[32];
    #pragma unroll
    for(int i=0;i<32;i++) wreg[i] = Wb[e*DDIM + i*32 + lane];
    for(int j=0;j<4;j++){
        int b = j*8 + w;
        const float* hr = h + b*DDIM;
        float acc = 0.f;
        #pragma unroll
        for(int i=0;i<32;i++) acc = fmaf(wreg[i], hr[i*32+lane], acc);
        #pragma unroll
        for(int o=16;o>0;o>>=1) acc += __shfl_xor_sync(0xffffffffu, acc, o);
        if(lane==0) g_ws[b*DDIM + e] = acc;
    }
}

// Fused: weighted_H tile = enc_tile @ Wc^T (tf32 MMA), then
// score[r] += sum_d tanh(H + ws[b,d]) * Wa[d]   (atomicAdd per row per N-tile)
// A = enc [M=65536, K=1024] row-major, B^T = Wc [N=1024 rows, K cols] row-major
// (exactly mma.sync row.col layout).
__global__ __launch_bounds__(256) void score_kernel(const float* __restrict__ enc,
                                                    const float* __restrict__ Wc,
                                                    const float* __restrict__ Wa){
    __shared__ unsigned As[128*36];   // [m][k], stride 36 -> conflict-free frag reads
    __shared__ unsigned Bs[64*36];    // [n][k]
    const int tid  = threadIdx.x;
    const int lane = tid & 31, warp = tid >> 5;
    const int g = lane >> 2, t = lane & 3;     // mma groupID / threadID-in-group
    const int warpM = warp >> 1, warpN = warp & 1;   // 4x2 warps, 32x32 per warp
    const int rowBase = blockIdx.x * 128;
    const int colBase = blockIdx.y * 64;

    float acc[2][4][4];
    #pragma unroll
    for(int mf=0;mf<2;mf++)
        #pragma unroll
        for(int nf=0;nf<4;nf++)
            #pragma unroll
            for(int c=0;c<4;c++) acc[mf][nf][c] = 0.f;

    for(int k0=0; k0<E2; k0+=32){
        // A tile: 128x32 floats (4 float4 per thread)
        #pragma unroll
        for(int i=0;i<4;i++){
            int id  = i*256 + tid;
            int row = id >> 3, kq = (id & 7) << 2;
            float4 v = *reinterpret_cast<const float4*>(
                enc + (size_t)(rowBase+row)*E2 + k0 + kq);
            unsigned* p = &As[row*36 + kq];
            p[0]=f2tf32(v.x); p[1]=f2tf32(v.y); p[2]=f2tf32(v.z); p[3]=f2tf32(v.w);
        }
        // B tile: 64x32 floats (2 float4 per thread)
        #pragma unroll
        for(int i=0;i<2;i++){
            int id  = i*256 + tid;
            int row = id >> 3, kq = (id & 7) << 2;
            float4 v = *reinterpret_cast<const float4*>(
                Wc + (size_t)(colBase+row)*E2 + k0 + kq);
            unsigned* p = &Bs[row*36 + kq];
            p[0]=f2tf32(v.x); p[1]=f2tf32(v.y); p[2]=f2tf32(v.z); p[3]=f2tf32(v.w);
        }
        __syncthreads();
        #pragma unroll
        for(int kk=0;kk<32;kk+=8){
            unsigned a[2][4], bfr[4][2];
            #pragma unroll
            for(int mf=0;mf<2;mf++){
                int m = warpM*32 + mf*16 + g;
                a[mf][0] = As[m    *36 + kk + t];
                a[mf][1] = As[(m+8)*36 + kk + t];
                a[mf][2] = As[m    *36 + kk + t + 4];
                a[mf][3] = As[(m+8)*36 + kk + t + 4];
            }
            #pragma unroll
            for(int nf=0;nf<4;nf++){
                int n = warpN*32 + nf*8 + g;
                bfr[nf][0] = Bs[n*36 + kk + t];
                bfr[nf][1] = Bs[n*36 + kk + t + 4];
            }
            #pragma unroll
            for(int mf=0;mf<2;mf++)
                #pragma unroll
                for(int nf=0;nf<4;nf++){
                    asm volatile(
                      "mma.sync.aligned.m16n8k8.row.col.f32.tf32.tf32.f32 "
                      "{%0,%1,%2,%3}, {%4,%5,%6,%7}, {%8,%9}, {%0,%1,%2,%3};\n"
                      : "+f"(acc[mf][nf][0]), "+f"(acc[mf][nf][1]),
                        "+f"(acc[mf][nf][2]), "+f"(acc[mf][nf][3])
                      : "r"(a[mf][0]), "r"(a[mf][1]), "r"(a[mf][2]), "r"(a[mf][3]),
                        "r"(bfr[nf][0]), "r"(bfr[nf][1]));
                }
        }
        __syncthreads();
    }

    // Epilogue: bias + tanh + Wa dot, reduce over the 64 d-columns of this tile.
    float rs[2][2] = {{0.f,0.f},{0.f,0.f}};
    #pragma unroll
    for(int mf=0;mf<2;mf++){
        int r0 = rowBase + warpM*32 + mf*16 + g;      // c0/c1 row
        const float* ws0 = g_ws + (size_t)( r0      & 31)*DDIM;
        const float* ws1 = g_ws + (size_t)((r0 + 8) & 31)*DDIM;
        #pragma unroll
        for(int nf=0;nf<4;nf++){
            int d0 = colBase + warpN*32 + nf*8 + t*2;
            float wa0 = __ldg(Wa + d0), wa1 = __ldg(Wa + d0 + 1);
            rs[mf][0] += fast_tanh(acc[mf][nf][0] + ws0[d0  ]) * wa0
                       + fast_tanh(acc[mf][nf][1] + ws0[d0+1]) * wa1;
            rs[mf][1] += fast_tanh(acc[mf][nf][2] + ws1[d0  ]) * wa0
                       + fast_tanh(acc[mf][nf][3] + ws1[d0+1]) * wa1;
        }
    }
    #pragma unroll
    for(int mf=0;mf<2;mf++)
        #pragma unroll
        for(int hh=0;hh<2;hh++){
            float v = rs[mf][hh];
            v += __shfl_xor_sync(0xffffffffu, v, 1);
            v += __shfl_xor_sync(0xffffffffu, v, 2);
            if(t==0){
                int r = rowBase + warpM*32 + mf*16 + hh*8 + g;
                atomicAdd(&g_score[r], v);
            }
        }
}

// Softmax over s for each b (score laid out r = s*32 + b).
__global__ __launch_bounds__(256) void softmax_kernel(){
    __shared__ float red[256];
    int b = blockIdx.x, tid = threadIdx.x;
    float m = -3.4e38f;
    for(int s=tid;s<SLEN;s+=256) m = fmaxf(m, g_score[s*BATCH+b]);
    red[tid]=m; __syncthreads();
    for(int o=128;o>0;o>>=1){ if(tid<o) red[tid]=fmaxf(red[tid],red[tid+o]); __syncthreads(); }
    m = red[0]; __syncthreads();
    float sum = 0.f;
    for(int s=tid;s<SLEN;s+=256){
        float e = __expf(g_score[s*BATCH+b]-m);
        g_attn[s*BATCH+b] = e; sum += e;
    }
    red[tid]=sum; __syncthreads();
    for(int o=128;o>0;o>>=1){ if(tid<o) red[tid]+=red[tid+o]; __syncthreads(); }
    float inv = 1.f/red[0];
    for(int s=tid;s<SLEN;s+=256) g_attn[s*BATCH+b] *= inv;
}

// context[b,e] = sum_s attn[s,b] * enc[s,b,e]  (atomic partial over s-chunks)
__global__ __launch_bounds__(256) void context_kernel(const float* __restrict__ enc,
                                                      float* __restrict__ out){
    int e  = blockIdx.x*256 + threadIdx.x;
    int b  = blockIdx.y;
    int s0 = blockIdx.z*128;
    float accv = 0.f;
    #pragma unroll 4
    for(int s=s0;s<s0+128;s++)
        accv = fmaf(g_attn[s*BATCH+b], enc[(size_t)(s*BATCH+b)*E2 + e], accv);
    atomicAdd(&out[b*E2+e], accv);
}

extern "C" void kernel_launch(void* const* d_in, const int* in_sizes, int n_in,
                              void* d_out, int out_size){
    const float* h   = (const float*)d_in[0];   // [B, D]
    const float* enc = (const float*)d_in[1];   // [S, B, E2]
    const float* Wb  = (const float*)d_in[2];   // [D, D]
    const float* Wc  = (const float*)d_in[3];   // [D, E2]
    const float* Wa  = (const float*)d_in[4];   // [D]
    float* out = (float*)d_out;                 // [1, B, E2]

    zero_kernel   <<<MROWS/256, 256>>>(out);
    ws_kernel     <<<DDIM, 256>>>(h, Wb);
    score_kernel  <<<dim3(MROWS/128, DDIM/64), 256>>>(enc, Wc, Wa);
    softmax_kernel<<<BATCH, 256>>>();
    context_kernel<<<dim3(E2/256, BATCH, SLEN/128), 256>>>(enc, out);
}

// round 4
// speedup vs baseline: 1.2416x; 1.2416x over previous
#include <cuda_runtime.h>
#include <cstdint>
#include <cstddef>

#define SLEN  2048
#define BATCH 32
#define DDIM  1024
#define E2V   1024
#define MROWS (SLEN*BATCH)

// score GEMM tiling
#define BM 256
#define BN 128
#define BK 32
#define NKI (E2V/BK)     // 32 k-iterations
#define NCB (DDIM/BN)    // 8 column blocks
#define NRB (MROWS/BM)   // 256 row blocks

// dynamic smem layout for score_kernel
#define OFF_A  0u          // 2 stages x 32768 B (packed A frags)
#define OFF_B  65536u      // 3 stages x 16384 B (packed B frags)
#define OFF_WA 114688u     // 128 floats
#define SMEM_TOTAL 115200u

// Device-global scratch (no runtime allocation allowed).
__device__ float g_ws[BATCH*DDIM];     // ws[b][d]
__device__ float g_score[MROWS];       // r = s*32+b
__device__ float g_attn[MROWS];
// Wc pre-converted to tf32 and pre-permuted into mma-fragment packing:
// entry = ((cb*8 + cp)*128 + kk8)*32 + lane, 4 floats per entry
__device__ __align__(16) float g_wcp[NCB*8*128*32*4];   // 4 MB

// ---------------------------------------------------------------- helpers
__device__ __forceinline__ uint32_t smem_u32(const void* p){
    uint32_t a;
    asm("{ .reg .u64 t; cvta.to.shared.u64 t, %1; cvt.u32.u64 %0, t; }"
        : "=r"(a) : "l"(p));
    return a;
}
__device__ __forceinline__ uint32_t f2tf32(float x){
    uint32_t r; asm("cvt.rna.tf32.f32 %0, %1;" : "=r"(r) : "f"(x)); return r;
}
__device__ __forceinline__ float fast_tanh(float x){
    float r; asm("tanh.approx.f32 %0, %1;" : "=f"(r) : "f"(x)); return r;
}
__device__ __forceinline__ void cp16(uint32_t dst, const void* src){
    asm volatile("cp.async.cg.shared.global [%0], [%1], 16;" :: "r"(dst), "l"(src));
}
__device__ __forceinline__ void lds128(uint32_t* r, uint32_t addr){
    asm volatile("ld.shared.v4.b32 {%0,%1,%2,%3}, [%4];"
                 : "=r"(r[0]), "=r"(r[1]), "=r"(r[2]), "=r"(r[3]) : "r"(addr));
}
__device__ __forceinline__ void sts32(uint32_t addr, uint32_t v){
    asm volatile("st.shared.b32 [%0], %1;" :: "r"(addr), "r"(v) : "memory");
}
__device__ __forceinline__ void mma_tf32(float* c, const uint32_t* a,
                                         uint32_t b0, uint32_t b1){
    asm volatile(
      "mma.sync.aligned.m16n8k8.row.col.f32.tf32.tf32.f32 "
      "{%0,%1,%2,%3}, {%4,%5,%6,%7}, {%8,%9}, {%0,%1,%2,%3};\n"
      : "+f"(c[0]), "+f"(c[1]), "+f"(c[2]), "+f"(c[3])
      : "r"(a[0]), "r"(a[1]), "r"(a[2]), "r"(a[3]), "r"(b0), "r"(b1));
}

// ---------------------------------------------------------------- kernels
__global__ void zero_kernel(float* __restrict__ out){
    int i = blockIdx.x*256 + threadIdx.x;
    if (i < MROWS)     g_score[i] = 0.f;
    if (i < BATCH*E2V) out[i]     = 0.f;
}

// Wc [1024 n][1024 k] fp32 -> tf32(rna), permuted into mma B-fragment packing.
// For element (n,kc): cb=n>>7, cp=(n>>4)&7, odd=(n>>3)&1, g=n&7,
// t=kc&3, half=(kc>>2)&1, kk8=kc>>3. entry=((cb*8+cp)*128+kk8)*32+g*4+t,
// slot = odd*2 + half.
__global__ __launch_bounds__(256) void wcpack_kernel(const float* __restrict__ Wc){
    int id = blockIdx.x*256 + threadIdx.x;      // 0..262143
    int n  = id >> 8;
    int k4 = (id & 255) << 2;
    const float4 v = *reinterpret_cast<const float4*>(Wc + (size_t)n*E2V + k4);
    uint32_t w[4] = { f2tf32(v.x), f2tf32(v.y), f2tf32(v.z), f2tf32(v.w) };
    int cb = n>>7, cp = (n>>4)&7, odd = (n>>3)&1, g = n&7;
    int kk8 = k4>>3, half = (k4>>2)&1;
    size_t ebase = (((size_t)(cb*8+cp)*128 + kk8)*32 + g*4);
    #pragma unroll
    for (int t=0;t<4;t++)
        *(uint32_t*)&g_wcp[(ebase + t)*4 + odd*2 + half] = w[t];
}

// ws[b][e] = sum_d h[b,d] * Wb[e,d]
__global__ __launch_bounds__(256) void ws_kernel(const float* __restrict__ h,
                                                 const float* __restrict__ Wb){
    int e    = blockIdx.x;
    int w    = threadIdx.x >> 5;
    int lane = threadIdx.x & 31;
    float wreg[32];
    #pragma unroll
    for (int i=0;i<32;i++) wreg[i] = Wb[(size_t)e*DDIM + i*32 + lane];
    for (int j=0;j<4;j++){
        int b = j*8 + w;
        const float* hr = h + (size_t)b*DDIM;
        float acc = 0.f;
        #pragma unroll
        for (int i=0;i<32;i++) acc = fmaf(wreg[i], hr[i*32+lane], acc);
        #pragma unroll
        for (int o=16;o>0;o>>=1) acc += __shfl_xor_sync(0xffffffffu, acc, o);
        if (lane==0) g_ws[(size_t)b*DDIM + e] = acc;
    }
}

// Fused pipelined tf32 score GEMM + tanh/Wa epilogue.
// Block: 256 rows x 128 cols, 512 threads (16 warps as 4x4, warp tile 64x32).
__global__ __launch_bounds__(512,1) void score_kernel(const float* __restrict__ enc,
                                                      const float* __restrict__ Wa){
    extern __shared__ char sm[];
    const uint32_t sb = smem_u32(sm);
    float* smf = (float*)sm;
    const int tid  = threadIdx.x;
    const int lane = tid & 31, warp = tid >> 5;
    const int g = lane >> 2, t = lane & 3;
    const int warpM = warp >> 2, warpN = warp & 3;
    const int cb      = blockIdx.x;                 // col block, fastest (L2 reuse of A)
    const size_t rowBase = (size_t)blockIdx.y * BM;
    const int colBase = cb * BN;

    if (tid < BN) smf[(OFF_WA>>2) + tid] = Wa[colBase + tid];

    // A-writer element mapping for this thread (4 float4 per tile)
    int arow[4], ak4[4]; uint32_t asts[4];
    #pragma unroll
    for (int i=0;i<4;i++){
        int f = tid + i*512;
        arow[i] = f >> 3;
        ak4[i]  = (f & 7) << 2;
        asts[i] = (uint32_t)(((((arow[i]>>4)*4 + (ak4[i]>>3))*32 + (arow[i]&7)*4)*16)
                 + ((arow[i]>>3)&1)*4 + ((ak4[i]>>2)&1)*8);
    }
    // B cp.async mapping (2 x 16B per thread per tile)
    int bcp[2], bkk[2], bln[2];
    #pragma unroll
    for (int i=0;i<2;i++){
        int e = tid*2 + i;
        bcp[i] = e >> 7; bkk[i] = (e>>5)&3; bln[i] = e & 31;
    }

    float4 st[4];
    // ---- prologue
    #pragma unroll
    for (int i=0;i<4;i++)
        st[i] = *reinterpret_cast<const float4*>(enc + (rowBase+arow[i])*E2V + ak4[i]);
    #pragma unroll
    for (int i=0;i<2;i++)
        cp16(sb + OFF_B + (uint32_t)((tid*2+i)*16),
             g_wcp + ((((size_t)(cb*8+bcp[i])*128) + 0*4 + bkk[i])*32 + bln[i])*4);
    asm volatile("cp.async.commit_group;" ::: "memory");     // G0
    {
        const uint32_t ab = sb + OFF_A;                      // stage 0
        #pragma unroll
        for (int i=0;i<4;i++){
            sts32(ab+asts[i]+ 0, f2tf32(st[i].x));
            sts32(ab+asts[i]+16, f2tf32(st[i].y));
            sts32(ab+asts[i]+32, f2tf32(st[i].z));
            sts32(ab+asts[i]+48, f2tf32(st[i].w));
        }
    }
    #pragma unroll
    for (int i=0;i<4;i++)
        st[i] = *reinterpret_cast<const float4*>(enc + (rowBase+arow[i])*E2V + BK + ak4[i]);
    #pragma unroll
    for (int i=0;i<2;i++)
        cp16(sb + OFF_B + 16384u + (uint32_t)((tid*2+i)*16),
             g_wcp + ((((size_t)(cb*8+bcp[i])*128) + 1*4 + bkk[i])*32 + bln[i])*4);
    asm volatile("cp.async.commit_group;" ::: "memory");     // G1

    float acc[4][4][4];
    #pragma unroll
    for (int mf=0;mf<4;mf++)
        #pragma unroll
        for (int nf=0;nf<4;nf++)
            #pragma unroll
            for (int c=0;c<4;c++) acc[mf][nf][c] = 0.f;

    // ---- main loop
    for (int kb=0; kb<NKI; kb++){
        asm volatile("cp.async.wait_group 1;" ::: "memory");
        __syncthreads();
        if (kb+1 < NKI){
            const uint32_t ab = sb + OFF_A + (uint32_t)(((kb+1)&1)*32768);
            #pragma unroll
            for (int i=0;i<4;i++){
                sts32(ab+asts[i]+ 0, f2tf32(st[i].x));
                sts32(ab+asts[i]+16, f2tf32(st[i].y));
                sts32(ab+asts[i]+32, f2tf32(st[i].z));
                sts32(ab+asts[i]+48, f2tf32(st[i].w));
            }
        }
        if (kb+2 < NKI){
            #pragma unroll
            for (int i=0;i<4;i++)
                st[i] = *reinterpret_cast<const float4*>(
                    enc + (rowBase+arow[i])*E2V + (kb+2)*BK + ak4[i]);
            const uint32_t bbst = sb + OFF_B + (uint32_t)(((kb+2)%3)*16384);
            #pragma unroll
            for (int i=0;i<2;i++)
                cp16(bbst + (uint32_t)((tid*2+i)*16),
                     g_wcp + ((((size_t)(cb*8+bcp[i])*128) + (kb+2)*4 + bkk[i])*32 + bln[i])*4);
        }
        asm volatile("cp.async.commit_group;" ::: "memory");

        const uint32_t Ab = sb + OFF_A + (uint32_t)((kb&1)*32768);
        const uint32_t Bb = sb + OFF_B + (uint32_t)((kb%3)*16384);
        #pragma unroll
        for (int ks=0; ks<4; ks++){
            uint32_t a[4][4], bq[2][4];
            #pragma unroll
            for (int mf=0;mf<4;mf++)
                lds128(a[mf], Ab + (uint32_t)((((warpM*4+mf)*4 + ks)*32 + lane)*16));
            #pragma unroll
            for (int p=0;p<2;p++)
                lds128(bq[p], Bb + (uint32_t)((((warpN*2+p)*4 + ks)*32 + lane)*16));
            #pragma unroll
            for (int mf=0;mf<4;mf++)
                #pragma unroll
                for (int nf=0;nf<4;nf++)
                    mma_tf32(acc[mf][nf], a[mf], bq[nf>>1][(nf&1)*2], bq[nf>>1][(nf&1)*2+1]);
        }
    }

    // ---- epilogue: tanh(H + ws) . Wa, row-reduce, atomic into g_score
    #pragma unroll
    for (int mf=0;mf<4;mf++){
        const int r0 = warpM*64 + mf*16 + g;        // local row (hh=0)
        const float* ws0 = g_ws + (size_t)( r0      & 31)*DDIM;
        const float* ws1 = g_ws + (size_t)((r0 + 8) & 31)*DDIM;
        float s0 = 0.f, s1 = 0.f;
        #pragma unroll
        for (int nf=0;nf<4;nf++){
            const int dl = warpN*32 + nf*8 + t*2;
            const int d0 = colBase + dl;
            const float wa0 = smf[(OFF_WA>>2) + dl];
            const float wa1 = smf[(OFF_WA>>2) + dl + 1];
            s0 += fast_tanh(acc[mf][nf][0] + ws0[d0  ]) * wa0
                + fast_tanh(acc[mf][nf][1] + ws0[d0+1]) * wa1;
            s1 += fast_tanh(acc[mf][nf][2] + ws1[d0  ]) * wa0
                + fast_tanh(acc[mf][nf][3] + ws1[d0+1]) * wa1;
        }
        s0 += __shfl_xor_sync(0xffffffffu, s0, 1);
        s0 += __shfl_xor_sync(0xffffffffu, s0, 2);
        s1 += __shfl_xor_sync(0xffffffffu, s1, 1);
        s1 += __shfl_xor_sync(0xffffffffu, s1, 2);
        if (t == 0){
            atomicAdd(&g_score[rowBase + r0    ], s0);
            atomicAdd(&g_score[rowBase + r0 + 8], s1);
        }
    }
}

// Single-pass softmax over s per batch b (2048 elems, 8 per thread).
__global__ __launch_bounds__(256) void softmax_kernel(){
    __shared__ float red[8];
    int b = blockIdx.x, tid = threadIdx.x;
    float v[8]; float m = -3.4e38f;
    #pragma unroll
    for (int i=0;i<8;i++){ v[i] = g_score[(i*256+tid)*BATCH + b]; m = fmaxf(m, v[i]); }
    #pragma unroll
    for (int o=16;o>0;o>>=1) m = fmaxf(m, __shfl_xor_sync(0xffffffffu, m, o));
    if ((tid&31)==0) red[tid>>5] = m;
    __syncthreads();
    float mm = red[0];
    #pragma unroll
    for (int i=1;i<8;i++) mm = fmaxf(mm, red[i]);
    __syncthreads();
    float ssum = 0.f;
    #pragma unroll
    for (int i=0;i<8;i++){ v[i] = __expf(v[i]-mm); ssum += v[i]; }
    #pragma unroll
    for (int o=16;o>0;o>>=1) ssum += __shfl_xor_sync(0xffffffffu, ssum, o);
    if ((tid&31)==0) red[tid>>5] = ssum;
    __syncthreads();
    float tot = 0.f;
    #pragma unroll
    for (int i=0;i<8;i++) tot += red[i];
    float inv = 1.f/tot;
    #pragma unroll
    for (int i=0;i<8;i++) g_attn[(i*256+tid)*BATCH + b] = v[i]*inv;
}

// context[b,e] = sum_s attn[s,b] * enc[s,b,e]
__global__ __launch_bounds__(256) void context_kernel(const float* __restrict__ enc,
                                                      float* __restrict__ out){
    int e  = blockIdx.x*256 + threadIdx.x;
    int b  = blockIdx.y;
    int s0 = blockIdx.z*128;
    float accv = 0.f;
    #pragma unroll 4
    for (int s=s0; s<s0+128; s++)
        accv = fmaf(g_attn[s*BATCH+b], enc[(size_t)(s*BATCH+b)*E2V + e], accv);
    atomicAdd(&out[b*E2V+e], accv);
}

extern "C" void kernel_launch(void* const* d_in, const int* in_sizes, int n_in,
                              void* d_out, int out_size){
    const float* h   = (const float*)d_in[0];   // [B, D]
    const float* enc = (const float*)d_in[1];   // [S, B, E2]
    const float* Wb  = (const float*)d_in[2];   // [D, D]
    const float* Wc  = (const float*)d_in[3];   // [D, E2]
    const float* Wa  = (const float*)d_in[4];   // [D]
    float* out = (float*)d_out;                 // [1, B, E2]

    cudaFuncSetAttribute(score_kernel,
                         cudaFuncAttributeMaxDynamicSharedMemorySize, SMEM_TOTAL);

    zero_kernel   <<<MROWS/256, 256>>>(out);
    wcpack_kernel <<<1024, 256>>>(Wc);
    ws_kernel     <<<DDIM, 256>>>(h, Wb);
    score_kernel  <<<dim3(NCB, NRB), 512, SMEM_TOTAL>>>(enc, Wa);
    softmax_kernel<<<BATCH, 256>>>();
    context_kernel<<<dim3(E2V/256, BATCH, SLEN/128), 256>>>(enc, out);
}

// round 6
// speedup vs baseline: 2.8040x; 2.2584x over previous
#include <cuda_runtime.h>
#include <cuda_fp16.h>
#include <cstdint>
#include <cstddef>

#define SLEN  2048
#define BATCH 32
#define DDIM  1024
#define E2V   1024
#define MROWS (SLEN*BATCH)

// score GEMM tiling: block 256x128, 8 warps (4x2), warp tile 64x64, BK=32
#define BM 256
#define BN 128
#define BK 32
#define NKI (E2V/BK)     // 32 k-iterations
#define NCB (DDIM/BN)    // 8 column blocks
#define NRB (MROWS/BM)   // 256 row blocks

// dynamic smem: 3-stage A (16KB) + 3-stage B (8KB) + Wa
#define OFF_A   0u
#define OFF_B   49152u
#define OFF_WA  73728u
#define SMEM_TOTAL 74240u

// Device-global scratch (no runtime allocation allowed).
__device__ float g_ws[BATCH*DDIM];     // ws[b][d]
__device__ float g_score[MROWS];       // r = s*32+b
__device__ float g_attn[MROWS];
// enc pre-converted fp16, mma-A-fragment packed: per (rowblk,kb) 16KB tile
__device__ __align__(16) __half g_apack[(size_t)MROWS*E2V];   // 128 MB
// Wc pre-converted fp16, mma-B-fragment packed: per (cb,kb) 8KB tile
__device__ __align__(16) __half g_wcb[(size_t)DDIM*E2V];      // 2 MB

// ---------------------------------------------------------------- helpers
__device__ __forceinline__ uint32_t smem_u32(const void* p){
    uint32_t a;
    asm("{ .reg .u64 t; cvta.to.shared.u64 t, %1; cvt.u32.u64 %0, t; }"
        : "=r"(a) : "l"(p));
    return a;
}
__device__ __forceinline__ float fast_tanh(float x){
    float r; asm("tanh.approx.f32 %0, %1;" : "=f"(r) : "f"(x)); return r;
}
__device__ __forceinline__ void cp16(uint32_t dst, const void* src){
    asm volatile("cp.async.cg.shared.global [%0], [%1], 16;" :: "r"(dst), "l"(src));
}
__device__ __forceinline__ void lds128(uint32_t* r, uint32_t addr){
    asm volatile("ld.shared.v4.b32 {%0,%1,%2,%3}, [%4];"
                 : "=r"(r[0]), "=r"(r[1]), "=r"(r[2]), "=r"(r[3]) : "r"(addr));
}
__device__ __forceinline__ void mma_f16(float* c, const uint32_t* a,
                                        uint32_t b0, uint32_t b1){
    asm volatile(
      "mma.sync.aligned.m16n8k16.row.col.f32.f16.f16.f32 "
      "{%0,%1,%2,%3}, {%4,%5,%6,%7}, {%8,%9}, {%0,%1,%2,%3};\n"
      : "+f"(c[0]), "+f"(c[1]), "+f"(c[2]), "+f"(c[3])
      : "r"(a[0]), "r"(a[1]), "r"(a[2]), "r"(a[3]), "r"(b0), "r"(b1));
}

// ---------------------------------------------------------------- kernels
__global__ void zero_kernel(float* __restrict__ out){
    int i = blockIdx.x*256 + threadIdx.x;
    if (i < MROWS)     g_score[i] = 0.f;
    if (i < BATCH*E2V) out[i]     = 0.f;
}

// enc [65536 rows][1024 k] fp32 -> fp16 A-fragment packed.
// Tile = (rowblk R: 256 rows) x (kb: 32 k) -> 16KB contiguous:
// frag f = (mgrp*2+ks)*32 + lane; 16B = {A[r0][2t..],A[r0+8][2t..],A[r0][2t+8..],A[r0+8][2t+8..]}
// with r0 = mgrp*16 + (lane>>2), k base = kb*32 + ks*16, t = lane&3.
__global__ __launch_bounds__(256) void apack_kernel(const float* __restrict__ enc){
    __shared__ __half2 s2[256][17];
    const int R = blockIdx.x, kb = blockIdx.y;
    const int tid = threadIdx.x;
    const float* src = enc + (size_t)R*256*E2V + kb*BK;
    #pragma unroll
    for (int j=0;j<8;j++){
        int idx = tid + j*256;               // 0..2047 float4s
        int row = idx >> 3, kq = (idx & 7) << 2;
        float4 v = *reinterpret_cast<const float4*>(src + (size_t)row*E2V + kq);
        s2[row][(kq>>1)  ] = __floats2half2_rn(v.x, v.y);
        s2[row][(kq>>1)+1] = __floats2half2_rn(v.z, v.w);
    }
    __syncthreads();
    uint4* outp = (uint4*)((char*)g_apack + (size_t)(R*32 + kb)*16384);
    #pragma unroll
    for (int j=0;j<4;j++){
        int f = tid + j*256;                 // 0..1023 fragments
        int lane = f & 31, ks = (f>>5)&1, mgrp = f>>6;
        int g = lane >> 2, t = lane & 3;
        int r0 = mgrp*16 + g, c = ks*8 + t;
        uint32_t q0 = *(const uint32_t*)&s2[r0  ][c  ];
        uint32_t q1 = *(const uint32_t*)&s2[r0+8][c  ];
        uint32_t q2 = *(const uint32_t*)&s2[r0  ][c+4];
        uint32_t q3 = *(const uint32_t*)&s2[r0+8][c+4];
        outp[f] = make_uint4(q0,q1,q2,q3);
    }
}

// Wc [1024 n][1024 k] fp32 -> fp16 B-fragment packed.
// Tile = (cb: 128 n) x (kb: 32 k) -> 8KB: frag16B at ((ngrp2*2+ks)*32 + g*4 + t)*16:
// {B[n0][2t..], B[n0][2t+8..], B[n0+8][2t..], B[n0+8][2t+8..]}, n0 = ngrp2*16+g(+s8*8).
__global__ __launch_bounds__(256) void wcpack_kernel(const float* __restrict__ Wc){
    int id = blockIdx.x*256 + threadIdx.x;   // 0..262143
    int n  = id >> 8;
    int k4 = (id & 255) << 2;
    float4 v = *reinterpret_cast<const float4*>(Wc + (size_t)n*E2V + k4);
    __half2 p01 = __floats2half2_rn(v.x, v.y);
    __half2 p23 = __floats2half2_rn(v.z, v.w);
    int cb = n >> 7, n7 = n & 127;
    int ngrp2 = n7 >> 4, s8 = (n7>>3)&1, g = n7 & 7;
    int kb = k4 >> 5, kk = k4 & 31;
    int ks = kk >> 4, kk16 = kk & 15;
    int t  = (kk16 & 7) >> 1, bh = kk16 >> 3;
    size_t base = (size_t)(cb*32 + kb)*8192
                + (size_t)(((ngrp2*2+ks)*32 + g*4 + t)*16 + s8*8 + bh*4);
    *(uint32_t*)((char*)g_wcb + base     ) = *(uint32_t*)&p01;
    *(uint32_t*)((char*)g_wcb + base + 16) = *(uint32_t*)&p23;
}

// ws[b][e] = sum_d h[b,d] * Wb[e,d]
__global__ __launch_bounds__(256) void ws_kernel(const float* __restrict__ h,
                                                 const float* __restrict__ Wb){
    int e    = blockIdx.x;
    int w    = threadIdx.x >> 5;
    int lane = threadIdx.x & 31;
    float wreg[32];
    #pragma unroll
    for (int i=0;i<32;i++) wreg[i] = Wb[(size_t)e*DDIM + i*32 + lane];
    for (int j=0;j<4;j++){
        int b = j*8 + w;
        const float* hr = h + (size_t)b*DDIM;
        float acc = 0.f;
        #pragma unroll
        for (int i=0;i<32;i++) acc = fmaf(wreg[i], hr[i*32+lane], acc);
        #pragma unroll
        for (int o=16;o>0;o>>=1) acc += __shfl_xor_sync(0xffffffffu, acc, o);
        if (lane==0) g_ws[(size_t)b*DDIM + e] = acc;
    }
}

// Fused fp16-MMA score GEMM + tanh/Wa epilogue. 256 threads, 8 warps (4x2),
// warp tile 64x64. All operands pre-packed; mainloop = cp.async + LDS + MMA.
__global__ __launch_bounds__(256,1) void score_kernel(const float* __restrict__ Wa){
    extern __shared__ char sm[];
    const uint32_t sb = smem_u32(sm);
    float* smf = (float*)sm;
    const int tid  = threadIdx.x;
    const int lane = tid & 31, warp = tid >> 5;
    const int g = lane >> 2, t = lane & 3;
    const int warpM = warp >> 1, warpN = warp & 1;
    const int cb = blockIdx.x;
    const int rb = blockIdx.y;
    const size_t rowBase = (size_t)rb * BM;
    const int colBase = cb * BN;

    if (tid < BN) smf[(OFF_WA>>2) + tid] = Wa[colBase + tid];

    const char* abase = (const char*)g_apack + (size_t)rb*32*16384;
    const char* bbase = (const char*)g_wcb   + (size_t)cb*32*8192;

    // prologue: stages 0,1
    #pragma unroll
    for (int s=0;s<2;s++){
        #pragma unroll
        for (int i=0;i<4;i++)
            cp16(sb + OFF_A + s*16384u + (uint32_t)(tid*16 + i*4096),
                 abase + (size_t)s*16384 + tid*16 + i*4096);
        #pragma unroll
        for (int i=0;i<2;i++)
            cp16(sb + OFF_B + s*8192u + (uint32_t)(tid*16 + i*4096),
                 bbase + (size_t)s*8192 + tid*16 + i*4096);
        asm volatile("cp.async.commit_group;" ::: "memory");
    }

    float acc[4][8][4];
    #pragma unroll
    for (int mf=0;mf<4;mf++)
        #pragma unroll
        for (int nf=0;nf<8;nf++)
            #pragma unroll
            for (int c=0;c<4;c++) acc[mf][nf][c] = 0.f;

    for (int kb=0; kb<NKI; kb++){
        asm volatile("cp.async.wait_group 1;" ::: "memory");
        __syncthreads();
        if (kb+2 < NKI){
            const int s = (kb+2)%3;
            #pragma unroll
            for (int i=0;i<4;i++)
                cp16(sb + OFF_A + s*16384u + (uint32_t)(tid*16 + i*4096),
                     abase + (size_t)(kb+2)*16384 + tid*16 + i*4096);
            #pragma unroll
            for (int i=0;i<2;i++)
                cp16(sb + OFF_B + s*8192u + (uint32_t)(tid*16 + i*4096),
                     bbase + (size_t)(kb+2)*8192 + tid*16 + i*4096);
        }
        asm volatile("cp.async.commit_group;" ::: "memory");

        const uint32_t Ab = sb + OFF_A + (uint32_t)((kb%3)*16384);
        const uint32_t Bb = sb + OFF_B + (uint32_t)((kb%3)*8192);
        #pragma unroll
        for (int ks=0; ks<2; ks++){
            uint32_t a[4][4], bq[4][4];
            #pragma unroll
            for (int mf=0;mf<4;mf++)
                lds128(a[mf], Ab + (uint32_t)((((warpM*4+mf)*2 + ks)*32 + lane)*16));
            #pragma unroll
            for (int p=0;p<4;p++)
                lds128(bq[p], Bb + (uint32_t)((((warpN*4+p)*2 + ks)*32 + lane)*16));
            #pragma unroll
            for (int mf=0;mf<4;mf++)
                #pragma unroll
                for (int nf=0;nf<8;nf++)
                    mma_f16(acc[mf][nf], a[mf],
                            bq[nf>>1][(nf&1)*2], bq[nf>>1][(nf&1)*2+1]);
        }
    }

    // epilogue: tanh(H + ws) . Wa, row-reduce over t, atomic into g_score
    #pragma unroll
    for (int mf=0;mf<4;mf++){
        const int r0 = warpM*64 + mf*16 + g;
        const float* ws0 = g_ws + (size_t)( r0      & 31)*DDIM;
        const float* ws1 = g_ws + (size_t)((r0 + 8) & 31)*DDIM;
        float s0 = 0.f, s1 = 0.f;
        #pragma unroll
        for (int nf=0;nf<8;nf++){
            const int dl = warpN*64 + nf*8 + t*2;
            const int d0 = colBase + dl;
            const float wa0 = smf[(OFF_WA>>2) + dl];
            const float wa1 = smf[(OFF_WA>>2) + dl + 1];
            s0 += fast_tanh(acc[mf][nf][0] + ws0[d0  ]) * wa0
                + fast_tanh(acc[mf][nf][1] + ws0[d0+1]) * wa1;
            s1 += fast_tanh(acc[mf][nf][2] + ws1[d0  ]) * wa0
                + fast_tanh(acc[mf][nf][3] + ws1[d0+1]) * wa1;
        }
        s0 += __shfl_xor_sync(0xffffffffu, s0, 1);
        s0 += __shfl_xor_sync(0xffffffffu, s0, 2);
        s1 += __shfl_xor_sync(0xffffffffu, s1, 1);
        s1 += __shfl_xor_sync(0xffffffffu, s1, 2);
        if (t == 0){
            atomicAdd(&g_score[rowBase + r0    ], s0);
            atomicAdd(&g_score[rowBase + r0 + 8], s1);
        }
    }
}

// Single-pass softmax over s per batch b.
__global__ __launch_bounds__(256) void softmax_kernel(){
    __shared__ float red[8];
    int b = blockIdx.x, tid = threadIdx.x;
    float v[8]; float m = -3.4e38f;
    #pragma unroll
    for (int i=0;i<8;i++){ v[i] = g_score[(i*256+tid)*BATCH + b]; m = fmaxf(m, v[i]); }
    #pragma unroll
    for (int o=16;o>0;o>>=1) m = fmaxf(m, __shfl_xor_sync(0xffffffffu, m, o));
    if ((tid&31)==0) red[tid>>5] = m;
    __syncthreads();
    float mm = red[0];
    #pragma unroll
    for (int i=1;i<8;i++) mm = fmaxf(mm, red[i]);
    __syncthreads();
    float ssum = 0.f;
    #pragma unroll
    for (int i=0;i<8;i++){ v[i] = __expf(v[i]-mm); ssum += v[i]; }
    #pragma unroll
    for (int o=16;o>0;o>>=1) ssum += __shfl_xor_sync(0xffffffffu, ssum, o);
    if ((tid&31)==0) red[tid>>5] = ssum;
    __syncthreads();
    float tot = 0.f;
    #pragma unroll
    for (int i=0;i<8;i++) tot += red[i];
    float inv = 1.f/tot;
    #pragma unroll
    for (int i=0;i<8;i++) g_attn[(i*256+tid)*BATCH + b] = v[i]*inv;
}

// context[b,e] = sum_s attn[s,b] * enc[s,b,e]
__global__ __launch_bounds__(256) void context_kernel(const float* __restrict__ enc,
                                                      float* __restrict__ out){
    int e  = blockIdx.x*256 + threadIdx.x;
    int b  = blockIdx.y;
    int s0 = blockIdx.z*128;
    float accv = 0.f;
    #pragma unroll 4
    for (int s=s0; s<s0+128; s++)
        accv = fmaf(g_attn[s*BATCH+b], enc[(size_t)(s*BATCH+b)*E2V + e], accv);
    atomicAdd(&out[b*E2V+e], accv);
}

extern "C" void kernel_launch(void* const* d_in, const int* in_sizes, int n_in,
                              void* d_out, int out_size){
    const float* h   = (const float*)d_in[0];   // [B, D]
    const float* enc = (const float*)d_in[1];   // [S, B, E2]
    const float* Wb  = (const float*)d_in[2];   // [D, D]
    const float* Wc  = (const float*)d_in[3];   // [D, E2]
    const float* Wa  = (const float*)d_in[4];   // [D]
    float* out = (float*)d_out;                 // [1, B, E2]

    cudaFuncSetAttribute(score_kernel,
                         cudaFuncAttributeMaxDynamicSharedMemorySize, SMEM_TOTAL);

    zero_kernel   <<<MROWS/256, 256>>>(out);
    wcpack_kernel <<<1024, 256>>>(Wc);
    apack_kernel  <<<dim3(NRB, NKI), 256>>>(enc);
    ws_kernel     <<<DDIM, 256>>>(h, Wb);
    score_kernel  <<<dim3(NCB, NRB), 256, SMEM_TOTAL>>>(Wa);
    softmax_kernel<<<BATCH, 256>>>();
    context_kernel<<<dim3(E2V/256, BATCH, SLEN/128), 256>>>(enc, out);
}

// round 10
// speedup vs baseline: 2.8362x; 1.0115x over previous
#include <cuda_runtime.h>
#include <cuda_fp16.h>
#include <cstdint>
#include <cstddef>

#define SLEN  2048
#define BATCH 32
#define DDIM  1024
#define E2V   1024
#define MROWS (SLEN*BATCH)

// score GEMM tiling: block 256x128, 8 warps (4x2), warp tile 64x64, BK=64
#define BM 256
#define BN 128
#define BK 64
#define NKI (E2V/BK)     // 16 k-iterations
#define NCB (DDIM/BN)    // 8 column blocks
#define NRB (MROWS/BM)   // 256 row blocks

// dynamic smem: 3-stage A (32KB) + 3-stage B (16KB) + Wa
#define OFF_A   0u
#define OFF_B   98304u
#define OFF_WA  147456u
#define SMEM_TOTAL 147968u

// fused prepass grid ranges
#define PB_APACK  8192           // 256 rowblks x 32 kb
#define PB_WCPACK 1024
#define PB_WS     1024
#define PB_ZERO   256
#define PB_TOTAL  (PB_APACK+PB_WCPACK+PB_WS+PB_ZERO)

// Device-global scratch (no runtime allocation allowed).
__device__ float g_ws[BATCH*DDIM];     // ws[b][d]
__device__ float g_score[MROWS];       // r = s*32+b
__device__ float g_attn[MROWS];
// enc pre-converted fp16, mma-A-fragment packed: per (rowblk,kb32) 16KB tile
__device__ __align__(16) __half g_apack[(size_t)MROWS*E2V];   // 128 MB
// Wc pre-converted fp16, mma-B-fragment packed: per (cb,kb32) 8KB tile
__device__ __align__(16) __half g_wcb[(size_t)DDIM*E2V];      // 2 MB

// ---------------------------------------------------------------- helpers
__device__ __forceinline__ uint32_t smem_u32(const void* p){
    uint32_t a;
    asm("{ .reg .u64 t; cvta.to.shared.u64 t, %1; cvt.u32.u64 %0, t; }"
        : "=r"(a) : "l"(p));
    return a;
}
__device__ __forceinline__ float fast_tanh(float x){
    float r; asm("tanh.approx.f32 %0, %1;" : "=f"(r) : "f"(x)); return r;
}
__device__ __forceinline__ void cp16(uint32_t dst, const void* src){
    asm volatile("cp.async.cg.shared.global [%0], [%1], 16;" :: "r"(dst), "l"(src));
}
__device__ __forceinline__ void lds128(uint32_t* r, uint32_t addr){
    asm volatile("ld.shared.v4.b32 {%0,%1,%2,%3}, [%4];"
                 : "=r"(r[0]), "=r"(r[1]), "=r"(r[2]), "=r"(r[3]) : "r"(addr));
}
__device__ __forceinline__ void mma_f16(float* c, const uint32_t* a,
                                        uint32_t b0, uint32_t b1){
    asm volatile(
      "mma.sync.aligned.m16n8k16.row.col.f32.f16.f16.f32 "
      "{%0,%1,%2,%3}, {%4,%5,%6,%7}, {%8,%9}, {%0,%1,%2,%3};\n"
      : "+f"(c[0]), "+f"(c[1]), "+f"(c[2]), "+f"(c[3])
      : "r"(a[0]), "r"(a[1]), "r"(a[2]), "r"(a[3]), "r"(b0), "r"(b1));
}

// ---------------------------------------------------------------- prepass bodies
// enc [rows][1024] fp32 -> fp16 A-fragment packed 16KB tiles (per rowblk,kb32).
__device__ void apack_body(const float* __restrict__ enc, int R, int kb,
                           __half2 (*s2)[17], int tid){
    const float* src = enc + (size_t)R*256*E2V + kb*32;
    #pragma unroll
    for (int j=0;j<8;j++){
        int idx = tid + j*256;               // 0..2047 float4s
        int row = idx >> 3, kq = (idx & 7) << 2;
        float4 v = *reinterpret_cast<const float4*>(src + (size_t)row*E2V + kq);
        s2[row][(kq>>1)  ] = __floats2half2_rn(v.x, v.y);
        s2[row][(kq>>1)+1] = __floats2half2_rn(v.z, v.w);
    }
    __syncthreads();
    uint4* outp = (uint4*)((char*)g_apack + (size_t)(R*32 + kb)*16384);
    #pragma unroll
    for (int j=0;j<4;j++){
        int f = tid + j*256;                 // 0..1023 fragments
        int lane = f & 31, ks = (f>>5)&1, mgrp = f>>6;
        int g = lane >> 2, t = lane & 3;
        int r0 = mgrp*16 + g, c = ks*8 + t;
        uint32_t q0 = *(const uint32_t*)&s2[r0  ][c  ];
        uint32_t q1 = *(const uint32_t*)&s2[r0+8][c  ];
        uint32_t q2 = *(const uint32_t*)&s2[r0  ][c+4];
        uint32_t q3 = *(const uint32_t*)&s2[r0+8][c+4];
        outp[f] = make_uint4(q0,q1,q2,q3);
    }
}

// Wc [1024 n][1024 k] fp32 -> fp16 B-fragment packed 8KB tiles (per cb,kb32).
__device__ void wcpack_body(const float* __restrict__ Wc, int blk, int tid){
    int id = blk*256 + tid;                  // 0..262143
    int n  = id >> 8;
    int k4 = (id & 255) << 2;
    float4 v = *reinterpret_cast<const float4*>(Wc + (size_t)n*E2V + k4);
    __half2 p01 = __floats2half2_rn(v.x, v.y);
    __half2 p23 = __floats2half2_rn(v.z, v.w);
    int cb = n >> 7, n7 = n & 127;
    int ngrp2 = n7 >> 4, s8 = (n7>>3)&1, g = n7 & 7;
    int kb = k4 >> 5, kk = k4 & 31;
    int ks = kk >> 4, kk16 = kk & 15;
    int t  = (kk16 & 7) >> 1, bh = kk16 >> 3;
    size_t base = (size_t)(cb*32 + kb)*8192
                + (size_t)(((ngrp2*2+ks)*32 + g*4 + t)*16 + s8*8 + bh*4);
    *(uint32_t*)((char*)g_wcb + base     ) = *(uint32_t*)&p01;
    *(uint32_t*)((char*)g_wcb + base + 16) = *(uint32_t*)&p23;
}

// ws[b][e] = sum_d h[b,d] * Wb[e,d]
__device__ void ws_body(const float* __restrict__ h, const float* __restrict__ Wb,
                        int e, int tid){
    int w    = tid >> 5;
    int lane = tid & 31;
    float wreg[32];
    #pragma unroll
    for (int i=0;i<32;i++) wreg[i] = Wb[(size_t)e*DDIM + i*32 + lane];
    for (int j=0;j<4;j++){
        int b = j*8 + w;
        const float* hr = h + (size_t)b*DDIM;
        float acc = 0.f;
        #pragma unroll
        for (int i=0;i<32;i++) acc = fmaf(wreg[i], hr[i*32+lane], acc);
        #pragma unroll
        for (int o=16;o>0;o>>=1) acc += __shfl_xor_sync(0xffffffffu, acc, o);
        if (lane==0) g_ws[(size_t)b*DDIM + e] = acc;
    }
}

__device__ void zero_body(float* __restrict__ out, int blk, int tid){
    int i = blk*256 + tid;
    if (i < MROWS)     g_score[i] = 0.f;
    if (i < BATCH*E2V) out[i]     = 0.f;
}

// One launch; block ranges dispatch to independent prepass jobs.
__global__ __launch_bounds__(256) void prepass_kernel(
        const float* __restrict__ enc, const float* __restrict__ Wc,
        const float* __restrict__ h,   const float* __restrict__ Wb,
        float* __restrict__ out){
    __shared__ __half2 s2[256][17];
    const int bx = blockIdx.x, tid = threadIdx.x;
    if (bx < PB_APACK){
        apack_body(enc, bx >> 5, bx & 31, s2, tid);
    } else if (bx < PB_APACK + PB_WCPACK){
        wcpack_body(Wc, bx - PB_APACK, tid);
    } else if (bx < PB_APACK + PB_WCPACK + PB_WS){
        ws_body(h, Wb, bx - (PB_APACK + PB_WCPACK), tid);
    } else {
        zero_body(out, bx - (PB_APACK + PB_WCPACK + PB_WS), tid);
    }
}

// ---------------------------------------------------------------- score
// Fused fp16-MMA score GEMM + tanh/Wa epilogue. 256 threads, 8 warps (4x2),
// warp tile 64x64, BK=64 (two packed 32-k tiles per stage, contiguous).
__global__ __launch_bounds__(256,1) void score_kernel(const float* __restrict__ Wa){
    extern __shared__ char sm[];
    const uint32_t sb = smem_u32(sm);
    float* smf = (float*)sm;
    const int tid  = threadIdx.x;
    const int lane = tid & 31, warp = tid >> 5;
    const int g = lane >> 2, t = lane & 3;
    const int warpM = warp >> 1, warpN = warp & 1;
    const int cb = blockIdx.x;
    const int rb = blockIdx.y;
    const size_t rowBase = (size_t)rb * BM;
    const int colBase = cb * BN;

    if (tid < BN) smf[(OFF_WA>>2) + tid] = Wa[colBase + tid];

    const char* abase = (const char*)g_apack + (size_t)rb*524288;  // 32 tiles x 16KB
    const char* bbase = (const char*)g_wcb   + (size_t)cb*262144;  // 32 tiles x 8KB

    // prologue: stages 0,1 (each 32KB A + 16KB B)
    #pragma unroll
    for (int s=0;s<2;s++){
        #pragma unroll
        for (int i=0;i<8;i++)
            cp16(sb + OFF_A + s*32768u + (uint32_t)(tid*16 + i*4096),
                 abase + (size_t)s*32768 + tid*16 + i*4096);
        #pragma unroll
        for (int i=0;i<4;i++)
            cp16(sb + OFF_B + s*16384u + (uint32_t)(tid*16 + i*4096),
                 bbase + (size_t)s*16384 + tid*16 + i*4096);
        asm volatile("cp.async.commit_group;" ::: "memory");
    }

    float acc[4][8][4];
    #pragma unroll
    for (int mf=0;mf<4;mf++)
        #pragma unroll
        for (int nf=0;nf<8;nf++)
            #pragma unroll
            for (int c=0;c<4;c++) acc[mf][nf][c] = 0.f;

    for (int kb=0; kb<NKI; kb++){
        asm volatile("cp.async.wait_group 1;" ::: "memory");
        __syncthreads();
        if (kb+2 < NKI){
            const int s = (kb+2)%3;
            #pragma unroll
            for (int i=0;i<8;i++)
                cp16(sb + OFF_A + s*32768u + (uint32_t)(tid*16 + i*4096),
                     abase + (size_t)(kb+2)*32768 + tid*16 + i*4096);
            #pragma unroll
            for (int i=0;i<4;i++)
                cp16(sb + OFF_B + s*16384u + (uint32_t)(tid*16 + i*4096),
                     bbase + (size_t)(kb+2)*16384 + tid*16 + i*4096);
        }
        asm volatile("cp.async.commit_group;" ::: "memory");

        const uint32_t Ab = sb + OFF_A + (uint32_t)((kb%3)*32768);
        const uint32_t Bb = sb + OFF_B + (uint32_t)((kb%3)*16384);
        #pragma unroll
        for (int ks=0; ks<4; ks++){
            const uint32_t kseg = (uint32_t)(ks>>1), kk = (uint32_t)(ks&1);
            uint32_t a[4][4], bq[4][4];
            #pragma unroll
            for (int mf=0;mf<4;mf++)
                lds128(a[mf], Ab + kseg*16384u
                       + (uint32_t)((((warpM*4+mf)*2 + kk)*32 + lane)*16));
            #pragma unroll
            for (int p=0;p<4;p++)
                lds128(bq[p], Bb + kseg*8192u
                       + (uint32_t)((((warpN*4+p)*2 + kk)*32 + lane)*16));
            #pragma unroll
            for (int mf=0;mf<4;mf++)
                #pragma unroll
                for (int nf=0;nf<8;nf++)
                    mma_f16(acc[mf][nf], a[mf],
                            bq[nf>>1][(nf&1)*2], bq[nf>>1][(nf&1)*2+1]);
        }
    }

    // epilogue: tanh(H + ws) . Wa, row-reduce over t, atomic into g_score
    #pragma unroll
    for (int mf=0;mf<4;mf++){
        const int r0 = warpM*64 + mf*16 + g;
        const float* ws0 = g_ws + (size_t)( r0      & 31)*DDIM;
        const float* ws1 = g_ws + (size_t)((r0 + 8) & 31)*DDIM;
        float s0 = 0.f, s1 = 0.f;
        #pragma unroll
        for (int nf=0;nf<8;nf++){
            const int dl = warpN*64 + nf*8 + t*2;
            const int d0 = colBase + dl;
            const float wa0 = smf[(OFF_WA>>2) + dl];
            const float wa1 = smf[(OFF_WA>>2) + dl + 1];
            s0 += fast_tanh(acc[mf][nf][0] + ws0[d0  ]) * wa0
                + fast_tanh(acc[mf][nf][1] + ws0[d0+1]) * wa1;
            s1 += fast_tanh(acc[mf][nf][2] + ws1[d0  ]) * wa0
                + fast_tanh(acc[mf][nf][3] + ws1[d0+1]) * wa1;
        }
        s0 += __shfl_xor_sync(0xffffffffu, s0, 1);
        s0 += __shfl_xor_sync(0xffffffffu, s0, 2);
        s1 += __shfl_xor_sync(0xffffffffu, s1, 1);
        s1 += __shfl_xor_sync(0xffffffffu, s1, 2);
        if (t == 0){
            atomicAdd(&g_score[rowBase + r0    ], s0);
            atomicAdd(&g_score[rowBase + r0 + 8], s1);
        }
    }
}

// Single-pass softmax over s per batch b.
__global__ __launch_bounds__(256) void softmax_kernel(){
    __shared__ float red[8];
    int b = blockIdx.x, tid = threadIdx.x;
    float v[8]; float m = -3.4e38f;
    #pragma unroll
    for (int i=0;i<8;i++){ v[i] = g_score[(i*256+tid)*BATCH + b]; m = fmaxf(m, v[i]); }
    #pragma unroll
    for (int o=16;o>0;o>>=1) m = fmaxf(m, __shfl_xor_sync(0xffffffffu, m, o));
    if ((tid&31)==0) red[tid>>5] = m;
    __syncthreads();
    float mm = red[0];
    #pragma unroll
    for (int i=1;i<8;i++) mm = fmaxf(mm, red[i]);
    __syncthreads();
    float ssum = 0.f;
    #pragma unroll
    for (int i=0;i<8;i++){ v[i] = __expf(v[i]-mm); ssum += v[i]; }
    #pragma unroll
    for (int o=16;o>0;o>>=1) ssum += __shfl_xor_sync(0xffffffffu, ssum, o);
    if ((tid&31)==0) red[tid>>5] = ssum;
    __syncthreads();
    float tot = 0.f;
    #pragma unroll
    for (int i=0;i<8;i++) tot += red[i];
    float inv = 1.f/tot;
    #pragma unroll
    for (int i=0;i<8;i++) g_attn[(i*256+tid)*BATCH + b] = v[i]*inv;
}

// context[b,e] = sum_s attn[s,b] * enc[s,b,e], float4, 256-s chunks.
__global__ __launch_bounds__(256) void context_kernel(const float* __restrict__ enc,
                                                      float* __restrict__ out){
    int e4 = threadIdx.x << 2;            // 0..1020
    int b  = blockIdx.y;
    int s0 = blockIdx.z << 8;             // 256 s per chunk
    float4 acc = make_float4(0.f,0.f,0.f,0.f);
    #pragma unroll 4
    for (int s=s0; s<s0+256; s++){
        float w = g_attn[s*BATCH+b];
        float4 v = *reinterpret_cast<const float4*>(
            enc + (size_t)(s*BATCH+b)*E2V + e4);
        acc.x = fmaf(w, v.x, acc.x);
        acc.y = fmaf(w, v.y, acc.y);
        acc.z = fmaf(w, v.z, acc.z);
        acc.w = fmaf(w, v.w, acc.w);
    }
    float* o = out + (size_t)b*E2V + e4;
    atomicAdd(o+0, acc.x); atomicAdd(o+1, acc.y);
    atomicAdd(o+2, acc.z); atomicAdd(o+3, acc.w);
}

extern "C" void kernel_launch(void* const* d_in, const int* in_sizes, int n_in,
                              void* d_out, int out_size){
    const float* h   = (const float*)d_in[0];   // [B, D]
    const float* enc = (const float*)d_in[1];   // [S, B, E2]
    const float* Wb  = (const float*)d_in[2];   // [D, D]
    const float* Wc  = (const float*)d_in[3];   // [D, E2]
    const float* Wa  = (const float*)d_in[4];   // [D]
    float* out = (float*)d_out;                 // [1, B, E2]

    cudaFuncSetAttribute(score_kernel,
                         cudaFuncAttributeMaxDynamicSharedMemorySize, SMEM_TOTAL);

    prepass_kernel<<<PB_TOTAL, 256>>>(enc, Wc, h, Wb, out);
    score_kernel  <<<dim3(NCB, NRB), 256, SMEM_TOTAL>>>(Wa);
    softmax_kernel<<<BATCH, 256>>>();
    context_kernel<<<dim3(1, BATCH, SLEN/256), 256>>>(enc, out);
}

// round 11
// speedup vs baseline: 2.9602x; 1.0437x over previous
#include <cuda_runtime.h>
#include <cuda_fp16.h>
#include <cstdint>
#include <cstddef>

#define SLEN  2048
#define BATCH 32
#define DDIM  1024
#define E2V   1024
#define MROWS (SLEN*BATCH)

// score GEMM tiling: block 256x128, 8 warps (4x2), warp tile 64x64, BK=64
#define BM 256
#define BN 128
#define BK 64
#define NKI (E2V/BK)     // 16 k-iterations
#define NCB (DDIM/BN)    // 8 column blocks
#define NRB (MROWS/BM)   // 256 row blocks

// dynamic smem: 3-stage A (32KB) + 3-stage B (16KB) + Wa
#define OFF_A   0u
#define OFF_B   98304u
#define OFF_WA  147456u
#define SMEM_TOTAL 147968u

// fused prepass grid ranges
#define PB_APACK  8192           // 256 rowblks x 32 kb
#define PB_WCPACK 1024
#define PB_WS     1024
#define PB_ZERO   256
#define PB_TOTAL  (PB_APACK+PB_WCPACK+PB_WS+PB_ZERO)

// Device-global scratch (no runtime allocation allowed).
__device__ float g_ws[BATCH*DDIM];     // ws[b][d]
__device__ float g_score[MROWS];       // r = s*32+b
__device__ float g_attn[MROWS];
// enc pre-converted fp16, mma-A-fragment packed: per (rowblk,kb32) 16KB tile
__device__ __align__(16) __half g_apack[(size_t)MROWS*E2V];   // 128 MB
// Wc pre-converted fp16, mma-B-fragment packed: per (cb,kb32) 8KB tile
__device__ __align__(16) __half g_wcb[(size_t)DDIM*E2V];      // 2 MB

// ---------------------------------------------------------------- helpers
__device__ __forceinline__ uint32_t smem_u32(const void* p){
    uint32_t a;
    asm("{ .reg .u64 t; cvta.to.shared.u64 t, %1; cvt.u32.u64 %0, t; }"
        : "=r"(a) : "l"(p));
    return a;
}
__device__ __forceinline__ float fast_tanh(float x){
    float r; asm("tanh.approx.f32 %0, %1;" : "=f"(r) : "f"(x)); return r;
}
__device__ __forceinline__ void cp16(uint32_t dst, const void* src){
    asm volatile("cp.async.cg.shared.global [%0], [%1], 16;" :: "r"(dst), "l"(src));
}
__device__ __forceinline__ void lds128(uint32_t* r, uint32_t addr){
    asm volatile("ld.shared.v4.b32 {%0,%1,%2,%3}, [%4];"
                 : "=r"(r[0]), "=r"(r[1]), "=r"(r[2]), "=r"(r[3]) : "r"(addr));
}
__device__ __forceinline__ void mma_f16(float* c, const uint32_t* a,
                                        uint32_t b0, uint32_t b1){
    asm volatile(
      "mma.sync.aligned.m16n8k16.row.col.f32.f16.f16.f32 "
      "{%0,%1,%2,%3}, {%4,%5,%6,%7}, {%8,%9}, {%0,%1,%2,%3};\n"
      : "+f"(c[0]), "+f"(c[1]), "+f"(c[2]), "+f"(c[3])
      : "r"(a[0]), "r"(a[1]), "r"(a[2]), "r"(a[3]), "r"(b0), "r"(b1));
}

// ---------------------------------------------------------------- prepass bodies
// enc [rows][1024] fp32 -> fp16 A-fragment packed 16KB tiles (per rowblk,kb32).
__device__ void apack_body(const float* __restrict__ enc, int R, int kb,
                           __half2 (*s2)[17], int tid){
    const float* src = enc + (size_t)R*256*E2V + kb*32;
    #pragma unroll
    for (int j=0;j<8;j++){
        int idx = tid + j*256;               // 0..2047 float4s
        int row = idx >> 3, kq = (idx & 7) << 2;
        float4 v = *reinterpret_cast<const float4*>(src + (size_t)row*E2V + kq);
        s2[row][(kq>>1)  ] = __floats2half2_rn(v.x, v.y);
        s2[row][(kq>>1)+1] = __floats2half2_rn(v.z, v.w);
    }
    __syncthreads();
    uint4* outp = (uint4*)((char*)g_apack + (size_t)(R*32 + kb)*16384);
    #pragma unroll
    for (int j=0;j<4;j++){
        int f = tid + j*256;                 // 0..1023 fragments
        int lane = f & 31, ks = (f>>5)&1, mgrp = f>>6;
        int g = lane >> 2, t = lane & 3;
        int r0 = mgrp*16 + g, c = ks*8 + t;
        uint32_t q0 = *(const uint32_t*)&s2[r0  ][c  ];
        uint32_t q1 = *(const uint32_t*)&s2[r0+8][c  ];
        uint32_t q2 = *(const uint32_t*)&s2[r0  ][c+4];
        uint32_t q3 = *(const uint32_t*)&s2[r0+8][c+4];
        outp[f] = make_uint4(q0,q1,q2,q3);
    }
}

// Wc [1024 n][1024 k] fp32 -> fp16 B-fragment packed 8KB tiles (per cb,kb32).
__device__ void wcpack_body(const float* __restrict__ Wc, int blk, int tid){
    int id = blk*256 + tid;                  // 0..262143
    int n  = id >> 8;
    int k4 = (id & 255) << 2;
    float4 v = *reinterpret_cast<const float4*>(Wc + (size_t)n*E2V + k4);
    __half2 p01 = __floats2half2_rn(v.x, v.y);
    __half2 p23 = __floats2half2_rn(v.z, v.w);
    int cb = n >> 7, n7 = n & 127;
    int ngrp2 = n7 >> 4, s8 = (n7>>3)&1, g = n7 & 7;
    int kb = k4 >> 5, kk = k4 & 31;
    int ks = kk >> 4, kk16 = kk & 15;
    int t  = (kk16 & 7) >> 1, bh = kk16 >> 3;
    size_t base = (size_t)(cb*32 + kb)*8192
                + (size_t)(((ngrp2*2+ks)*32 + g*4 + t)*16 + s8*8 + bh*4);
    *(uint32_t*)((char*)g_wcb + base     ) = *(uint32_t*)&p01;
    *(uint32_t*)((char*)g_wcb + base + 16) = *(uint32_t*)&p23;
}

// ws[b][e] = sum_d h[b,d] * Wb[e,d]
__device__ void ws_body(const float* __restrict__ h, const float* __restrict__ Wb,
                        int e, int tid){
    int w    = tid >> 5;
    int lane = tid & 31;
    float wreg[32];
    #pragma unroll
    for (int i=0;i<32;i++) wreg[i] = Wb[(size_t)e*DDIM + i*32 + lane];
    for (int j=0;j<4;j++){
        int b = j*8 + w;
        const float* hr = h + (size_t)b*DDIM;
        float acc = 0.f;
        #pragma unroll
        for (int i=0;i<32;i++) acc = fmaf(wreg[i], hr[i*32+lane], acc);
        #pragma unroll
        for (int o=16;o>0;o>>=1) acc += __shfl_xor_sync(0xffffffffu, acc, o);
        if (lane==0) g_ws[(size_t)b*DDIM + e] = acc;
    }
}

__device__ void zero_body(float* __restrict__ out, int blk, int tid){
    int i = blk*256 + tid;
    if (i < MROWS)     g_score[i] = 0.f;
    if (i < BATCH*E2V) out[i]     = 0.f;
}

// One launch; block ranges dispatch to independent prepass jobs.
__global__ __launch_bounds__(256) void prepass_kernel(
        const float* __restrict__ enc, const float* __restrict__ Wc,
        const float* __restrict__ h,   const float* __restrict__ Wb,
        float* __restrict__ out){
    __shared__ __half2 s2[256][17];
    const int bx = blockIdx.x, tid = threadIdx.x;
    if (bx < PB_APACK){
        apack_body(enc, bx >> 5, bx & 31, s2, tid);
    } else if (bx < PB_APACK + PB_WCPACK){
        wcpack_body(Wc, bx - PB_APACK, tid);
    } else if (bx < PB_APACK + PB_WCPACK + PB_WS){
        ws_body(h, Wb, bx - (PB_APACK + PB_WCPACK), tid);
    } else {
        zero_body(out, bx - (PB_APACK + PB_WCPACK + PB_WS), tid);
    }
}

// ---------------------------------------------------------------- score
// Fused fp16-MMA score GEMM + tanh/Wa epilogue. 256 threads, 8 warps (4x2),
// warp tile 64x64, BK=64 (two packed 32-k tiles per stage, contiguous).
__global__ __launch_bounds__(256,1) void score_kernel(const float* __restrict__ Wa){
    extern __shared__ char sm[];
    const uint32_t sb = smem_u32(sm);
    float* smf = (float*)sm;
    const int tid  = threadIdx.x;
    const int lane = tid & 31, warp = tid >> 5;
    const int g = lane >> 2, t = lane & 3;
    const int warpM = warp >> 1, warpN = warp & 1;
    const int cb = blockIdx.x;
    const int rb = blockIdx.y;
    const size_t rowBase = (size_t)rb * BM;
    const int colBase = cb * BN;

    if (tid < BN) smf[(OFF_WA>>2) + tid] = Wa[colBase + tid];

    const char* abase = (const char*)g_apack + (size_t)rb*524288;  // 32 tiles x 16KB
    const char* bbase = (const char*)g_wcb   + (size_t)cb*262144;  // 32 tiles x 8KB

    // prologue: stages 0,1 (each 32KB A + 16KB B)
    #pragma unroll
    for (int s=0;s<2;s++){
        #pragma unroll
        for (int i=0;i<8;i++)
            cp16(sb + OFF_A + s*32768u + (uint32_t)(tid*16 + i*4096),
                 abase + (size_t)s*32768 + tid*16 + i*4096);
        #pragma unroll
        for (int i=0;i<4;i++)
            cp16(sb + OFF_B + s*16384u + (uint32_t)(tid*16 + i*4096),
                 bbase + (size_t)s*16384 + tid*16 + i*4096);
        asm volatile("cp.async.commit_group;" ::: "memory");
    }

    float acc[4][8][4];
    #pragma unroll
    for (int mf=0;mf<4;mf++)
        #pragma unroll
        for (int nf=0;nf<8;nf++)
            #pragma unroll
            for (int c=0;c<4;c++) acc[mf][nf][c] = 0.f;

    for (int kb=0; kb<NKI; kb++){
        asm volatile("cp.async.wait_group 1;" ::: "memory");
        __syncthreads();
        if (kb+2 < NKI){
            const int s = (kb+2)%3;
            #pragma unroll
            for (int i=0;i<8;i++)
                cp16(sb + OFF_A + s*32768u + (uint32_t)(tid*16 + i*4096),
                     abase + (size_t)(kb+2)*32768 + tid*16 + i*4096);
            #pragma unroll
            for (int i=0;i<4;i++)
                cp16(sb + OFF_B + s*16384u + (uint32_t)(tid*16 + i*4096),
                     bbase + (size_t)(kb+2)*16384 + tid*16 + i*4096);
        }
        asm volatile("cp.async.commit_group;" ::: "memory");

        const uint32_t Ab = sb + OFF_A + (uint32_t)((kb%3)*32768);
        const uint32_t Bb = sb + OFF_B + (uint32_t)((kb%3)*16384);
        #pragma unroll
        for (int ks=0; ks<4; ks++){
            const uint32_t kseg = (uint32_t)(ks>>1), kk = (uint32_t)(ks&1);
            uint32_t a[4][4], bq[4][4];
            #pragma unroll
            for (int mf=0;mf<4;mf++)
                lds128(a[mf], Ab + kseg*16384u
                       + (uint32_t)((((warpM*4+mf)*2 + kk)*32 + lane)*16));
            #pragma unroll
            for (int p=0;p<4;p++)
                lds128(bq[p], Bb + kseg*8192u
                       + (uint32_t)((((warpN*4+p)*2 + kk)*32 + lane)*16));
            #pragma unroll
            for (int mf=0;mf<4;mf++)
                #pragma unroll
                for (int nf=0;nf<8;nf++)
                    mma_f16(acc[mf][nf], a[mf],
                            bq[nf>>1][(nf&1)*2], bq[nf>>1][(nf&1)*2+1]);
        }
    }

    // epilogue: tanh(H + ws) . Wa, row-reduce over t, atomic into g_score
    #pragma unroll
    for (int mf=0;mf<4;mf++){
        const int r0 = warpM*64 + mf*16 + g;
        const float* ws0 = g_ws + (size_t)( r0      & 31)*DDIM;
        const float* ws1 = g_ws + (size_t)((r0 + 8) & 31)*DDIM;
        float s0 = 0.f, s1 = 0.f;
        #pragma unroll
        for (int nf=0;nf<8;nf++){
            const int dl = warpN*64 + nf*8 + t*2;
            const int d0 = colBase + dl;
            const float wa0 = smf[(OFF_WA>>2) + dl];
            const float wa1 = smf[(OFF_WA>>2) + dl + 1];
            s0 += fast_tanh(acc[mf][nf][0] + ws0[d0  ]) * wa0
                + fast_tanh(acc[mf][nf][1] + ws0[d0+1]) * wa1;
            s1 += fast_tanh(acc[mf][nf][2] + ws1[d0  ]) * wa0
                + fast_tanh(acc[mf][nf][3] + ws1[d0+1]) * wa1;
        }
        s0 += __shfl_xor_sync(0xffffffffu, s0, 1);
        s0 += __shfl_xor_sync(0xffffffffu, s0, 2);
        s1 += __shfl_xor_sync(0xffffffffu, s1, 1);
        s1 += __shfl_xor_sync(0xffffffffu, s1, 2);
        if (t == 0){
            atomicAdd(&g_score[rowBase + r0    ], s0);
            atomicAdd(&g_score[rowBase + r0 + 8], s1);
        }
    }
}

// Single-pass softmax over s per batch b.
__global__ __launch_bounds__(256) void softmax_kernel(){
    __shared__ float red[8];
    int b = blockIdx.x, tid = threadIdx.x;
    float v[8]; float m = -3.4e38f;
    #pragma unroll
    for (int i=0;i<8;i++){ v[i] = g_score[(i*256+tid)*BATCH + b]; m = fmaxf(m, v[i]); }
    #pragma unroll
    for (int o=16;o>0;o>>=1) m = fmaxf(m, __shfl_xor_sync(0xffffffffu, m, o));
    if ((tid&31)==0) red[tid>>5] = m;
    __syncthreads();
    float mm = red[0];
    #pragma unroll
    for (int i=1;i<8;i++) mm = fmaxf(mm, red[i]);
    __syncthreads();
    float ssum = 0.f;
    #pragma unroll
    for (int i=0;i<8;i++){ v[i] = __expf(v[i]-mm); ssum += v[i]; }
    #pragma unroll
    for (int o=16;o>0;o>>=1) ssum += __shfl_xor_sync(0xffffffffu, ssum, o);
    if ((tid&31)==0) red[tid>>5] = ssum;
    __syncthreads();
    float tot = 0.f;
    #pragma unroll
    for (int i=0;i<8;i++) tot += red[i];
    float inv = 1.f/tot;
    #pragma unroll
    for (int i=0;i<8;i++) g_attn[(i*256+tid)*BATCH + b] = v[i]*inv;
}

// context[b,e] = sum_s attn[s,b] * enc[s,b,e], float4, 32-s chunks (2048 blocks).
__global__ __launch_bounds__(256) void context_kernel(const float* __restrict__ enc,
                                                      float* __restrict__ out){
    int e4 = threadIdx.x << 2;            // 0..1020
    int b  = blockIdx.y;
    int s0 = blockIdx.z << 5;             // 32 s per chunk
    float4 acc = make_float4(0.f,0.f,0.f,0.f);
    #pragma unroll 4
    for (int s=s0; s<s0+32; s++){
        float w = g_attn[s*BATCH+b];
        float4 v = *reinterpret_cast<const float4*>(
            enc + (size_t)(s*BATCH+b)*E2V + e4);
        acc.x = fmaf(w, v.x, acc.x);
        acc.y = fmaf(w, v.y, acc.y);
        acc.z = fmaf(w, v.z, acc.z);
        acc.w = fmaf(w, v.w, acc.w);
    }
    float* o = out + (size_t)b*E2V + e4;
    atomicAdd(o+0, acc.x); atomicAdd(o+1, acc.y);
    atomicAdd(o+2, acc.z); atomicAdd(o+3, acc.w);
}

extern "C" void kernel_launch(void* const* d_in, const int* in_sizes, int n_in,
                              void* d_out, int out_size){
    const float* h   = (const float*)d_in[0];   // [B, D]
    const float* enc = (const float*)d_in[1];   // [S, B, E2]
    const float* Wb  = (const float*)d_in[2];   // [D, D]
    const float* Wc  = (const float*)d_in[3];   // [D, E2]
    const float* Wa  = (const float*)d_in[4];   // [D]
    float* out = (float*)d_out;                 // [1, B, E2]

    cudaFuncSetAttribute(score_kernel,
                         cudaFuncAttributeMaxDynamicSharedMemorySize, SMEM_TOTAL);

    prepass_kernel<<<PB_TOTAL, 256>>>(enc, Wc, h, Wb, out);
    score_kernel  <<<dim3(NCB, NRB), 256, SMEM_TOTAL>>>(Wa);
    softmax_kernel<<<BATCH, 256>>>();
    context_kernel<<<dim3(1, BATCH, SLEN/32), 256>>>(enc, out);
}